// round 12
// baseline (speedup 1.0000x reference)
#include <cuda_runtime.h>

// ProdAt: x [16384, 8192] fp32 -> out [16384, 128] fp32
// out[seg] = prod of 64 contiguous floats.
//
// R12: byte-identical re-bench of R11 (reproducibility probe per rigor.md).
// R11 measured 76.5us wall — 3.5us below the stable 80-81.6us band of all
// prior variants — while ncu kernel dur (79.2us) and HBM (6867 GB/s) were
// unchanged. Verifying whether the 256-thread + packed-STG.64 shape's wall
// gain is real or a DVFS/noise draw before finalizing.
//
// Geometry:
//   8 lanes per segment; each lane loads f4[sub] and f4[sub+8] (each LDG.128
//   by an 8-lane group covers one full 128B line -> perfect coalescing).
//   Each thread handles 2 ADJACENT segments -> 4 independent LDG.128
//   front-batched (MLP=4); sub==0 lanes store a packed float2 (STG.64).
//   256-thread blocks, 32768 CTAs.

static constexpr long long N_SEGMENTS_TOTAL = 16384LL * 128LL;  // 2,097,152

__device__ __forceinline__ float prod4(float4 v) {
    return (v.x * v.y) * (v.z * v.w);
}

__global__ void __launch_bounds__(256) prodat_kernel(
    const float* __restrict__ x, float* __restrict__ out)
{
    const long long warp_id =
        (long long)blockIdx.x * (blockDim.x >> 5) + (threadIdx.x >> 5);
    const int lane = threadIdx.x & 31;

    const int g   = lane >> 3;   // 0..3 : segment-pair group within warp
    const int sub = lane & 7;    // 0..7 : float4 slot within segment half

    // warp covers 8 consecutive segments [warp_id*8, warp_id*8+8)
    // this thread: adjacent segments 2g and 2g+1
    const long long seg0 = warp_id * 8 + 2 * g;
    const long long seg1 = seg0 + 1;

    const float4* x4 = reinterpret_cast<const float4*>(x);

    // front-batch 4 independent loads (MLP = 4), streaming eviction
    const float4 a0 = __ldcs(x4 + seg0 * 16 + sub);
    const float4 b0 = __ldcs(x4 + seg0 * 16 + 8 + sub);
    const float4 a1 = __ldcs(x4 + seg1 * 16 + sub);
    const float4 b1 = __ldcs(x4 + seg1 * 16 + 8 + sub);

    float p0 = prod4(a0) * prod4(b0);
    float p1 = prod4(a1) * prod4(b1);

    // two independent 3-step reductions over the 8-lane group (pipelined)
    #pragma unroll
    for (int off = 4; off > 0; off >>= 1) {
        p0 *= __shfl_xor_sync(0xffffffffu, p0, off);
        p1 *= __shfl_xor_sync(0xffffffffu, p1, off);
    }

    if (sub == 0) {
        // packed 8B store of two adjacent segment results (STG.64)
        reinterpret_cast<float2*>(out)[seg0 >> 1] = make_float2(p0, p1);
    }
}

extern "C" void kernel_launch(void* const* d_in, const int* in_sizes, int n_in,
                              void* d_out, int out_size)
{
    const float* x = (const float*)d_in[0];
    float* out = (float*)d_out;

    // 256 threads = 8 warps = 64 segments per block
    const int threads = 256;
    const long long blocks = N_SEGMENTS_TOTAL / 64;  // 32768, exact

    prodat_kernel<<<(unsigned)blocks, threads>>>(x, out);
}

// round 13
// speedup vs baseline: 1.0024x; 1.0024x over previous
#include <cuda_runtime.h>

// ProdAt: x [16384, 8192] fp32 -> out [16384, 128] fp32
// out[seg] = prod of 64 contiguous floats.
//
// FINAL. Exhaustive search across R1-R12 (MLP 1/4/8 per thread, LDG.128 vs
// LDG.256, 256 vs 512 threads, persistent vs fire-and-forget grids, __ldcs /
// L2::256B hints, scattered vs packed stores) pinned every variant at
// 6.86-6.97 TB/s, ncu kernel dur 78-79.3us — the structural ceiling for a
// compulsory single-pass 512MB read (path-independent LTS byte cap /
// ~87% HBM efficiency). R11's 76.5us outlier failed byte-identical
// reproduction (R12: 80.6us) and was discarded per rigor.md.
//
// Geometry (best-reproduced wall: 80.0/80.4us):
//   8 lanes per segment; each lane loads f4[sub] and f4[sub+8] (each LDG.128
//   by an 8-lane group covers one full 128B line -> perfect coalescing).
//   Each thread handles 2 ADJACENT segments -> 4 independent LDG.128
//   front-batched (MLP=4); 3-step shfl_xor reduce over the 8-lane group;
//   sub==0 lanes store a packed float2 (STG.64, fully-covered 32B sectors).
//   512-thread blocks, 16384 CTAs.

static constexpr long long N_SEGMENTS_TOTAL = 16384LL * 128LL;  // 2,097,152

__device__ __forceinline__ float prod4(float4 v) {
    return (v.x * v.y) * (v.z * v.w);
}

__global__ void __launch_bounds__(512) prodat_kernel(
    const float* __restrict__ x, float* __restrict__ out)
{
    const long long warp_id =
        (long long)blockIdx.x * (blockDim.x >> 5) + (threadIdx.x >> 5);
    const int lane = threadIdx.x & 31;

    const int g   = lane >> 3;   // 0..3 : segment-pair group within warp
    const int sub = lane & 7;    // 0..7 : float4 slot within segment half

    // warp covers 8 consecutive segments [warp_id*8, warp_id*8+8)
    // this thread: adjacent segments 2g and 2g+1
    const long long seg0 = warp_id * 8 + 2 * g;
    const long long seg1 = seg0 + 1;

    const float4* x4 = reinterpret_cast<const float4*>(x);

    // front-batch 4 independent loads (MLP = 4), streaming eviction
    const float4 a0 = __ldcs(x4 + seg0 * 16 + sub);
    const float4 b0 = __ldcs(x4 + seg0 * 16 + 8 + sub);
    const float4 a1 = __ldcs(x4 + seg1 * 16 + sub);
    const float4 b1 = __ldcs(x4 + seg1 * 16 + 8 + sub);

    float p0 = prod4(a0) * prod4(b0);
    float p1 = prod4(a1) * prod4(b1);

    // two independent 3-step reductions over the 8-lane group (pipelined)
    #pragma unroll
    for (int off = 4; off > 0; off >>= 1) {
        p0 *= __shfl_xor_sync(0xffffffffu, p0, off);
        p1 *= __shfl_xor_sync(0xffffffffu, p1, off);
    }

    if (sub == 0) {
        // packed 8B store of two adjacent segment results (STG.64)
        reinterpret_cast<float2*>(out)[seg0 >> 1] = make_float2(p0, p1);
    }
}

extern "C" void kernel_launch(void* const* d_in, const int* in_sizes, int n_in,
                              void* d_out, int out_size)
{
    const float* x = (const float*)d_in[0];
    float* out = (float*)d_out;

    // 512 threads = 16 warps = 128 segments per block
    const int threads = 512;
    const long long blocks = N_SEGMENTS_TOTAL / 128;  // 16384, exact

    prodat_kernel<<<(unsigned)blocks, threads>>>(x, out);
}

// round 14
// speedup vs baseline: 1.0286x; 1.0261x over previous
#include <cuda_runtime.h>

// ProdAt: x [16384, 8192] fp32 -> out [16384, 128] fp32
// out[seg] = prod of 64 contiguous floats.
//
// R14: third sample of the 256-thread shape (byte-identical to R11/R12).
// R11 measured 76.5us wall, R12 (same binary) 80.6us; the 512-thread twin
// is triple-reproduced at 80.0/80.4/80.4us with identical ncu dur (~79us)
// and HBM (~6.9 TB/s) for both shapes. This run decides noise vs bimodal:
// <=78us => adopt this shape as final (2-of-3); else 512-thread R5 is final.
//
// Geometry:
//   8 lanes per segment; each lane loads f4[sub] and f4[sub+8] (each LDG.128
//   by an 8-lane group covers one full 128B line -> perfect coalescing).
//   Each thread handles 2 ADJACENT segments -> 4 independent LDG.128
//   front-batched (MLP=4); 3-step shfl_xor reduce over the 8-lane group;
//   sub==0 lanes store a packed float2 (STG.64). 256 threads, 32768 CTAs.

static constexpr long long N_SEGMENTS_TOTAL = 16384LL * 128LL;  // 2,097,152

__device__ __forceinline__ float prod4(float4 v) {
    return (v.x * v.y) * (v.z * v.w);
}

__global__ void __launch_bounds__(256) prodat_kernel(
    const float* __restrict__ x, float* __restrict__ out)
{
    const long long warp_id =
        (long long)blockIdx.x * (blockDim.x >> 5) + (threadIdx.x >> 5);
    const int lane = threadIdx.x & 31;

    const int g   = lane >> 3;   // 0..3 : segment-pair group within warp
    const int sub = lane & 7;    // 0..7 : float4 slot within segment half

    // warp covers 8 consecutive segments [warp_id*8, warp_id*8+8)
    // this thread: adjacent segments 2g and 2g+1
    const long long seg0 = warp_id * 8 + 2 * g;
    const long long seg1 = seg0 + 1;

    const float4* x4 = reinterpret_cast<const float4*>(x);

    // front-batch 4 independent loads (MLP = 4), streaming eviction
    const float4 a0 = __ldcs(x4 + seg0 * 16 + sub);
    const float4 b0 = __ldcs(x4 + seg0 * 16 + 8 + sub);
    const float4 a1 = __ldcs(x4 + seg1 * 16 + sub);
    const float4 b1 = __ldcs(x4 + seg1 * 16 + 8 + sub);

    float p0 = prod4(a0) * prod4(b0);
    float p1 = prod4(a1) * prod4(b1);

    // two independent 3-step reductions over the 8-lane group (pipelined)
    #pragma unroll
    for (int off = 4; off > 0; off >>= 1) {
        p0 *= __shfl_xor_sync(0xffffffffu, p0, off);
        p1 *= __shfl_xor_sync(0xffffffffu, p1, off);
    }

    if (sub == 0) {
        // packed 8B store of two adjacent segment results (STG.64)
        reinterpret_cast<float2*>(out)[seg0 >> 1] = make_float2(p0, p1);
    }
}

extern "C" void kernel_launch(void* const* d_in, const int* in_sizes, int n_in,
                              void* d_out, int out_size)
{
    const float* x = (const float*)d_in[0];
    float* out = (float*)d_out;

    // 256 threads = 8 warps = 64 segments per block
    const int threads = 256;
    const long long blocks = N_SEGMENTS_TOTAL / 64;  // 32768, exact

    prodat_kernel<<<(unsigned)blocks, threads>>>(x, out);
}